// round 1
// baseline (speedup 1.0000x reference)
#include <cuda_runtime.h>
#include <math.h>
#include <stdint.h>

// Problem constants
#define BB 128
#define NN 256
#define DD 512
#define OO 512
#define MROWS (BB * NN)   // 32768

// Scratch (no cudaMalloc allowed)
__device__ float g_ln[(size_t)MROWS * DD];   // LN output (reused for all 3 blocks)
__device__ float g_h1[(size_t)MROWS * OO];
__device__ float g_h2[(size_t)MROWS * OO];

// ---------------------------------------------------------------------------
// LayerNorm: one block per row (512 elems), 128 threads x float4.
// If x2 != nullptr, normalizes (x + x2) (residual path).
// ---------------------------------------------------------------------------
__global__ void ln_kernel(const float* __restrict__ x,
                          const float* __restrict__ x2,
                          const float* __restrict__ g,
                          const float* __restrict__ b,
                          float* __restrict__ y) {
    const int row = blockIdx.x;
    const int tid = threadIdx.x;  // 0..127

    float4 v = reinterpret_cast<const float4*>(x + (size_t)row * DD)[tid];
    if (x2 != nullptr) {
        float4 v2 = reinterpret_cast<const float4*>(x2 + (size_t)row * DD)[tid];
        v.x += v2.x; v.y += v2.y; v.z += v2.z; v.w += v2.w;
    }

    float s  = v.x + v.y + v.z + v.w;
    float ss = v.x * v.x + v.y * v.y + v.z * v.z + v.w * v.w;

    #pragma unroll
    for (int o = 16; o > 0; o >>= 1) {
        s  += __shfl_xor_sync(0xFFFFFFFFu, s,  o);
        ss += __shfl_xor_sync(0xFFFFFFFFu, ss, o);
    }

    __shared__ float sh_s[4], sh_ss[4];
    const int w = tid >> 5;
    if ((tid & 31) == 0) { sh_s[w] = s; sh_ss[w] = ss; }
    __syncthreads();
    s  = sh_s[0] + sh_s[1] + sh_s[2] + sh_s[3];
    ss = sh_ss[0] + sh_ss[1] + sh_ss[2] + sh_ss[3];

    const float mean = s * (1.0f / DD);
    const float var  = ss * (1.0f / DD) - mean * mean;
    const float r    = rsqrtf(var + 1e-5f);

    const float4 gv = reinterpret_cast<const float4*>(g)[tid];
    const float4 bv = reinterpret_cast<const float4*>(b)[tid];
    float4 o;
    o.x = (v.x - mean) * r * gv.x + bv.x;
    o.y = (v.y - mean) * r * gv.y + bv.y;
    o.z = (v.z - mean) * r * gv.z + bv.z;
    o.w = (v.w - mean) * r * gv.w + bv.w;
    reinterpret_cast<float4*>(y + (size_t)row * DD)[tid] = o;
}

// ---------------------------------------------------------------------------
// Classic SGEMM: C[M,N] = A[M,K] @ B[K,N], M=32768, N=K=512.
// 128x128 block tile, BK=8, 256 threads, 8x8 per thread.
// Optional tanh epilogue.
// ---------------------------------------------------------------------------
template <bool TANH>
__global__ __launch_bounds__(256)
void sgemm_kernel(const float* __restrict__ A,
                  const float* __restrict__ B,
                  float* __restrict__ C) {
    const int K = 512, N = 512;
    __shared__ float As[8][128];
    __shared__ float Bs[8][128];

    const int tid = threadIdx.x;
    const int m0 = blockIdx.y * 128;
    const int n0 = blockIdx.x * 128;

    const int aRow = tid >> 1;          // 0..127
    const int aCol = (tid & 1) * 4;     // 0 or 4
    const int bRow = tid >> 5;          // 0..7
    const int bCol = (tid & 31) * 4;    // 0..124

    const int tx = tid & 15;            // 0..15
    const int ty = tid >> 4;            // 0..15

    float acc[8][8];
    #pragma unroll
    for (int i = 0; i < 8; i++)
        #pragma unroll
        for (int j = 0; j < 8; j++) acc[i][j] = 0.0f;

    const float* Aptr = A + (size_t)(m0 + aRow) * K + aCol;
    const float* Bptr = B + (size_t)bRow * N + n0 + bCol;

    for (int k0 = 0; k0 < K; k0 += 8) {
        float4 av = *reinterpret_cast<const float4*>(Aptr + k0);
        float4 bv = *reinterpret_cast<const float4*>(Bptr + (size_t)k0 * N);

        As[aCol + 0][aRow] = av.x;
        As[aCol + 1][aRow] = av.y;
        As[aCol + 2][aRow] = av.z;
        As[aCol + 3][aRow] = av.w;
        *reinterpret_cast<float4*>(&Bs[bRow][bCol]) = bv;
        __syncthreads();

        #pragma unroll
        for (int k = 0; k < 8; k++) {
            float ra[8], rb[8];
            float4 a0 = *reinterpret_cast<const float4*>(&As[k][ty * 8]);
            float4 a1 = *reinterpret_cast<const float4*>(&As[k][ty * 8 + 4]);
            float4 b0 = *reinterpret_cast<const float4*>(&Bs[k][tx * 8]);
            float4 b1 = *reinterpret_cast<const float4*>(&Bs[k][tx * 8 + 4]);
            ra[0]=a0.x; ra[1]=a0.y; ra[2]=a0.z; ra[3]=a0.w;
            ra[4]=a1.x; ra[5]=a1.y; ra[6]=a1.z; ra[7]=a1.w;
            rb[0]=b0.x; rb[1]=b0.y; rb[2]=b0.z; rb[3]=b0.w;
            rb[4]=b1.x; rb[5]=b1.y; rb[6]=b1.z; rb[7]=b1.w;
            #pragma unroll
            for (int i = 0; i < 8; i++)
                #pragma unroll
                for (int j = 0; j < 8; j++)
                    acc[i][j] = fmaf(ra[i], rb[j], acc[i][j]);
        }
        __syncthreads();
    }

    #pragma unroll
    for (int i = 0; i < 8; i++) {
        float4 o0, o1;
        if (TANH) {
            o0.x = tanhf(acc[i][0]); o0.y = tanhf(acc[i][1]);
            o0.z = tanhf(acc[i][2]); o0.w = tanhf(acc[i][3]);
            o1.x = tanhf(acc[i][4]); o1.y = tanhf(acc[i][5]);
            o1.z = tanhf(acc[i][6]); o1.w = tanhf(acc[i][7]);
        } else {
            o0.x = acc[i][0]; o0.y = acc[i][1]; o0.z = acc[i][2]; o0.w = acc[i][3];
            o1.x = acc[i][4]; o1.y = acc[i][5]; o1.z = acc[i][6]; o1.w = acc[i][7];
        }
        size_t off = (size_t)(m0 + ty * 8 + i) * N + n0 + tx * 8;
        *reinterpret_cast<float4*>(C + off)     = o0;
        *reinterpret_cast<float4*>(C + off + 4) = o1;
    }
}

// ---------------------------------------------------------------------------
// Masked softmax over axis=1 (the N=256 dim), in-place on out[B, N, O].
// One block per batch b, 512 threads (one per output channel o).
// Handles the "grant at least one valid" rule; masked entries -> 0
// (equals reference: exp(finfo.min - max) == 0, nan_to_num no-op).
// Mask is read as 4-byte words: nonzero bits == valid works for both
// int32(1) and float32(1.0f) encodings of the bool mask.
// ---------------------------------------------------------------------------
__global__ __launch_bounds__(512)
void softmax_kernel(float* __restrict__ out, const unsigned* __restrict__ mask) {
    const int b = blockIdx.x;
    const int o = threadIdx.x;  // 0..511

    __shared__ unsigned smask[NN];
    if (threadIdx.x < NN) smask[threadIdx.x] = mask[(size_t)b * NN + threadIdx.x];
    __syncthreads();

    int my = (threadIdx.x < NN) ? (smask[threadIdx.x] != 0u) : 0;
    int any = __syncthreads_or(my);
    if (!any && threadIdx.x == 0) smask[0] = 1u;
    __syncthreads();

    float* base = out + (size_t)b * NN * OO + o;

    float m = -INFINITY;
    for (int n = 0; n < NN; n++)
        if (smask[n]) m = fmaxf(m, base[(size_t)n * OO]);

    float s = 0.0f;
    for (int n = 0; n < NN; n++)
        if (smask[n]) s += __expf(base[(size_t)n * OO] - m);

    const float rs = 1.0f / s;
    for (int n = 0; n < NN; n++) {
        float v = smask[n] ? __expf(base[(size_t)n * OO] - m) * rs : 0.0f;
        base[(size_t)n * OO] = v;
    }
}

// ---------------------------------------------------------------------------
// Launch: inputs per setup_inputs() order:
// 0 Observation, 1 mask, 2 g1, 3 b1, 4 W1, 5 g2, 6 b2, 7 W2, 8 g3, 9 b3, 10 W3
// ---------------------------------------------------------------------------
extern "C" void kernel_launch(void* const* d_in, const int* in_sizes, int n_in,
                              void* d_out, int out_size) {
    const float*    Obs  = (const float*)d_in[0];
    const unsigned* mask = (const unsigned*)d_in[1];
    const float* g1 = (const float*)d_in[2];
    const float* b1 = (const float*)d_in[3];
    const float* W1 = (const float*)d_in[4];
    const float* g2 = (const float*)d_in[5];
    const float* b2 = (const float*)d_in[6];
    const float* W2 = (const float*)d_in[7];
    const float* g3 = (const float*)d_in[8];
    const float* b3 = (const float*)d_in[9];
    const float* W3 = (const float*)d_in[10];
    float* out = (float*)d_out;

    float* ln = nullptr; float* h1 = nullptr; float* h2 = nullptr;
    cudaGetSymbolAddress((void**)&ln, g_ln);
    cudaGetSymbolAddress((void**)&h1, g_h1);
    cudaGetSymbolAddress((void**)&h2, g_h2);

    const dim3 gGemm(OO / 128, MROWS / 128);

    // Block 1: LN(x) @ W1 -> tanh
    ln_kernel<<<MROWS, 128>>>(Obs, nullptr, g1, b1, ln);
    sgemm_kernel<true><<<gGemm, 256>>>(ln, W1, h1);

    // Block 2: LN(h1) @ W2 -> tanh
    ln_kernel<<<MROWS, 128>>>(h1, nullptr, g2, b2, ln);
    sgemm_kernel<true><<<gGemm, 256>>>(ln, W2, h2);

    // Block 3: LN(h2 + h1) @ W3
    ln_kernel<<<MROWS, 128>>>(h2, h1, g3, b3, ln);
    sgemm_kernel<false><<<gGemm, 256>>>(ln, W3, out);

    // Masked softmax over axis=1, in place
    softmax_kernel<<<BB, 512>>>(out, mask);
}

// round 3
// speedup vs baseline: 2.3788x; 2.3788x over previous
#include <cuda_runtime.h>
#include <cuda_bf16.h>
#include <math.h>
#include <stdint.h>

#define BB 128
#define NN 256
#define DD 512
#define OO 512
#define MROWS (BB * NN)   // 32768

// ---------------------------------------------------------------------------
// Scratch (no cudaMalloc allowed)
// ---------------------------------------------------------------------------
__device__ float g_h1[(size_t)MROWS * OO];
__device__ float g_h2[(size_t)MROWS * OO];
__device__ __nv_bfloat16 g_a_hi[(size_t)MROWS * DD];
__device__ __nv_bfloat16 g_a_lo[(size_t)MROWS * DD];
__device__ __nv_bfloat16 g_w_hi[(size_t)DD * OO];   // W^T: [N][K] bf16
__device__ __nv_bfloat16 g_w_lo[(size_t)DD * OO];

// ---------------------------------------------------------------------------
// Small helpers (all plain sm_80-era PTX — valid under compute_103)
// ---------------------------------------------------------------------------
__device__ __forceinline__ uint32_t smem_to_u32(const void* p) {
    uint32_t a;
    asm("{ .reg .u64 t; cvta.to.shared.u64 t, %1; cvt.u32.u64 %0, t; }"
        : "=r"(a) : "l"(p));
    return a;
}
__device__ __forceinline__ void cp16(uint32_t dst, const void* src) {
    asm volatile("cp.async.cg.shared.global [%0], [%1], 16;"
                 :: "r"(dst), "l"(src) : "memory");
}
__device__ __forceinline__ uint32_t lds32(uint32_t addr) {
    uint32_t v;
    asm volatile("ld.shared.b32 %0, [%1];" : "=r"(v) : "r"(addr));
    return v;
}
__device__ __forceinline__ void mma_bf16(float* c, const uint32_t* a,
                                         uint32_t b0, uint32_t b1) {
    asm volatile(
        "mma.sync.aligned.m16n8k16.row.col.f32.bf16.bf16.f32 "
        "{%0,%1,%2,%3}, {%4,%5,%6,%7}, {%8,%9}, {%0,%1,%2,%3};"
        : "+f"(c[0]), "+f"(c[1]), "+f"(c[2]), "+f"(c[3])
        : "r"(a[0]), "r"(a[1]), "r"(a[2]), "r"(a[3]), "r"(b0), "r"(b1));
}

// SMEM tile layout: 128 rows x 32 bf16 (64B/row), 16B chunks XOR-swizzled:
// byte(row,k) = row*64 + (((k>>3) ^ (row&3)) << 4) + (k&7)*2
__device__ __forceinline__ uint32_t toff(int row, int k) {
    return (uint32_t)(row * 64 + ((((k >> 3) ^ (row & 3)) & 3) << 4) + ((k & 7) << 1));
}

// ---------------------------------------------------------------------------
// LayerNorm -> split-bf16 (hi + lo). Optional residual x2.
// ---------------------------------------------------------------------------
__global__ void ln_split_kernel(const float* __restrict__ x,
                                const float* __restrict__ x2,
                                const float* __restrict__ g,
                                const float* __restrict__ b,
                                __nv_bfloat16* __restrict__ yhi,
                                __nv_bfloat16* __restrict__ ylo) {
    const int row = blockIdx.x;
    const int tid = threadIdx.x;

    float4 v = reinterpret_cast<const float4*>(x + (size_t)row * DD)[tid];
    if (x2 != nullptr) {
        float4 v2 = reinterpret_cast<const float4*>(x2 + (size_t)row * DD)[tid];
        v.x += v2.x; v.y += v2.y; v.z += v2.z; v.w += v2.w;
    }

    float s  = v.x + v.y + v.z + v.w;
    float ss = v.x * v.x + v.y * v.y + v.z * v.z + v.w * v.w;
    #pragma unroll
    for (int o = 16; o > 0; o >>= 1) {
        s  += __shfl_xor_sync(0xFFFFFFFFu, s,  o);
        ss += __shfl_xor_sync(0xFFFFFFFFu, ss, o);
    }
    __shared__ float sh_s[4], sh_ss[4];
    const int w = tid >> 5;
    if ((tid & 31) == 0) { sh_s[w] = s; sh_ss[w] = ss; }
    __syncthreads();
    s  = sh_s[0] + sh_s[1] + sh_s[2] + sh_s[3];
    ss = sh_ss[0] + sh_ss[1] + sh_ss[2] + sh_ss[3];

    const float mean = s * (1.0f / DD);
    const float var  = ss * (1.0f / DD) - mean * mean;
    const float r    = rsqrtf(var + 1e-5f);

    const float4 gv = reinterpret_cast<const float4*>(g)[tid];
    const float4 bv = reinterpret_cast<const float4*>(b)[tid];
    float o0 = (v.x - mean) * r * gv.x + bv.x;
    float o1 = (v.y - mean) * r * gv.y + bv.y;
    float o2 = (v.z - mean) * r * gv.z + bv.z;
    float o3 = (v.w - mean) * r * gv.w + bv.w;

    __nv_bfloat16 h0 = __float2bfloat16(o0), h1 = __float2bfloat16(o1);
    __nv_bfloat16 h2 = __float2bfloat16(o2), h3 = __float2bfloat16(o3);
    __nv_bfloat16 l0 = __float2bfloat16(o0 - __bfloat162float(h0));
    __nv_bfloat16 l1 = __float2bfloat16(o1 - __bfloat162float(h1));
    __nv_bfloat16 l2 = __float2bfloat16(o2 - __bfloat162float(h2));
    __nv_bfloat16 l3 = __float2bfloat16(o3 - __bfloat162float(h3));

    __nv_bfloat162* ph = reinterpret_cast<__nv_bfloat162*>(yhi + (size_t)row * DD);
    __nv_bfloat162* pl = reinterpret_cast<__nv_bfloat162*>(ylo + (size_t)row * DD);
    ph[tid * 2]     = __nv_bfloat162(h0, h1);
    ph[tid * 2 + 1] = __nv_bfloat162(h2, h3);
    pl[tid * 2]     = __nv_bfloat162(l0, l1);
    pl[tid * 2 + 1] = __nv_bfloat162(l2, l3);
}

// ---------------------------------------------------------------------------
// Weight split+transpose: W[K,N] f32 -> Wt_hi/Wt_lo [N,K] bf16
// ---------------------------------------------------------------------------
__global__ void wsplit_kernel(const float* __restrict__ W,
                              __nv_bfloat16* __restrict__ hi,
                              __nv_bfloat16* __restrict__ lo) {
    int idx = blockIdx.x * 256 + threadIdx.x;
    int k = idx >> 9, n = idx & 511;
    float w = W[idx];
    __nv_bfloat16 h = __float2bfloat16(w);
    hi[(size_t)n * DD + k] = h;
    lo[(size_t)n * DD + k] = __float2bfloat16(w - __bfloat162float(h));
}

// ---------------------------------------------------------------------------
// Split-bf16 HMMA GEMM: C[M,N] = (Ahi+Alo)[M,K] @ (Bhi+Blo)^T, B in [N,K].
// CTA 128x128, BK=32, 2-stage cp.async double buffer, 8 warps (32x64 each).
// ---------------------------------------------------------------------------
template <bool TANH>
__global__ __launch_bounds__(256, 2)
void gemm_hmma_kernel(const __nv_bfloat16* __restrict__ Ahi,
                      const __nv_bfloat16* __restrict__ Alo,
                      const __nv_bfloat16* __restrict__ Bhi,
                      const __nv_bfloat16* __restrict__ Blo,
                      float* __restrict__ C) {
    extern __shared__ char smem[];
    const uint32_t sb = smem_to_u32(smem);
    // 4 arrays x 2 stages x 8192B
    const uint32_t SA_H = sb;
    const uint32_t SA_L = sb + 16384;
    const uint32_t SB_H = sb + 32768;
    const uint32_t SB_L = sb + 49152;

    const int tid  = threadIdx.x;
    const int lane = tid & 31;
    const int wid  = tid >> 5;
    const int m0 = blockIdx.y * 128;
    const int n0 = blockIdx.x * 128;
    const int warp_m = (wid >> 1) * 32;   // 0,32,64,96
    const int warp_n = (wid & 1) * 64;    // 0,64

    float acc[2][8][4];
    #pragma unroll
    for (int i = 0; i < 2; i++)
        #pragma unroll
        for (int j = 0; j < 8; j++)
            #pragma unroll
            for (int q = 0; q < 4; q++) acc[i][j][q] = 0.0f;

    // cp.async stage load: each thread moves 2 x 16B per array (8 cp.async)
    const int c0row = tid >> 2,          c0ch = tid & 3;
    const int c1row = (tid + 256) >> 2,  c1ch = tid & 3;   // (tid+256)&3 == tid&3
    const uint32_t d0 = (uint32_t)(c0row * 64 + ((c0ch ^ (c0row & 3)) << 4));
    const uint32_t d1 = (uint32_t)(c1row * 64 + ((c1ch ^ (c1row & 3)) << 4));
    const size_t gA0 = (size_t)(m0 + c0row) * DD + c0ch * 8;
    const size_t gA1 = (size_t)(m0 + c1row) * DD + c1ch * 8;
    const size_t gB0 = (size_t)(n0 + c0row) * DD + c0ch * 8;
    const size_t gB1 = (size_t)(n0 + c1row) * DD + c1ch * 8;

    #define LOAD_STAGE(it, buf) do {                                     \
        const int _k0 = (it) * 32;                                       \
        const uint32_t _so = (uint32_t)(buf) * 8192u;                    \
        cp16(SA_H + _so + d0, Ahi + gA0 + _k0);                          \
        cp16(SA_H + _so + d1, Ahi + gA1 + _k0);                          \
        cp16(SA_L + _so + d0, Alo + gA0 + _k0);                          \
        cp16(SA_L + _so + d1, Alo + gA1 + _k0);                          \
        cp16(SB_H + _so + d0, Bhi + gB0 + _k0);                          \
        cp16(SB_H + _so + d1, Bhi + gB1 + _k0);                          \
        cp16(SB_L + _so + d0, Blo + gB0 + _k0);                          \
        cp16(SB_L + _so + d1, Blo + gB1 + _k0);                          \
        asm volatile("cp.async.commit_group;" ::: "memory");             \
    } while (0)

    LOAD_STAGE(0, 0);

    const int NK = DD / 32;   // 16
    for (int it = 0; it < NK; it++) {
        if (it + 1 < NK) {
            LOAD_STAGE(it + 1, (it + 1) & 1);
            asm volatile("cp.async.wait_group 1;" ::: "memory");
        } else {
            asm volatile("cp.async.wait_group 0;" ::: "memory");
        }
        __syncthreads();

        const uint32_t so = (uint32_t)(it & 1) * 8192u;
        #pragma unroll
        for (int ks = 0; ks < 2; ks++) {
            const int kb = ks * 16;
            const int kk = kb + (lane & 3) * 2;
            // A fragments (hi and lo) for both m16 tiles
            uint32_t ah[2][4], al[2][4];
            #pragma unroll
            for (int mt = 0; mt < 2; mt++) {
                const int rA = warp_m + mt * 16 + (lane >> 2);
                const int rB = rA + 8;
                ah[mt][0] = lds32(SA_H + so + toff(rA, kk));
                ah[mt][1] = lds32(SA_H + so + toff(rB, kk));
                ah[mt][2] = lds32(SA_H + so + toff(rA, kk + 8));
                ah[mt][3] = lds32(SA_H + so + toff(rB, kk + 8));
                al[mt][0] = lds32(SA_L + so + toff(rA, kk));
                al[mt][1] = lds32(SA_L + so + toff(rB, kk));
                al[mt][2] = lds32(SA_L + so + toff(rA, kk + 8));
                al[mt][3] = lds32(SA_L + so + toff(rB, kk + 8));
            }
            #pragma unroll
            for (int j = 0; j < 8; j++) {
                const int rN = warp_n + j * 8 + (lane >> 2);
                const uint32_t bh0 = lds32(SB_H + so + toff(rN, kk));
                const uint32_t bh1 = lds32(SB_H + so + toff(rN, kk + 8));
                const uint32_t bl0 = lds32(SB_L + so + toff(rN, kk));
                const uint32_t bl1 = lds32(SB_L + so + toff(rN, kk + 8));
                #pragma unroll
                for (int mt = 0; mt < 2; mt++) {
                    mma_bf16(acc[mt][j], ah[mt], bh0, bh1);
                    mma_bf16(acc[mt][j], ah[mt], bl0, bl1);
                    mma_bf16(acc[mt][j], al[mt], bh0, bh1);
                }
            }
        }
        __syncthreads();
    }
    #undef LOAD_STAGE

    // Epilogue: direct global float2 stores
    #pragma unroll
    for (int mt = 0; mt < 2; mt++) {
        const int row = m0 + warp_m + mt * 16 + (lane >> 2);
        #pragma unroll
        for (int j = 0; j < 8; j++) {
            const int col = n0 + warp_n + j * 8 + (lane & 3) * 2;
            float v0 = acc[mt][j][0], v1 = acc[mt][j][1];
            float v2 = acc[mt][j][2], v3 = acc[mt][j][3];
            if (TANH) { v0 = tanhf(v0); v1 = tanhf(v1); v2 = tanhf(v2); v3 = tanhf(v3); }
            *reinterpret_cast<float2*>(C + (size_t)row * OO + col)       = make_float2(v0, v1);
            *reinterpret_cast<float2*>(C + (size_t)(row + 8) * OO + col) = make_float2(v2, v3);
        }
    }
}

// ---------------------------------------------------------------------------
// Masked softmax over axis=1 (N=256), in-place on out[B, N, O].
// ---------------------------------------------------------------------------
__global__ __launch_bounds__(512)
void softmax_kernel(float* __restrict__ out, const unsigned* __restrict__ mask) {
    const int b = blockIdx.x;
    const int o = threadIdx.x;

    __shared__ unsigned smask[NN];
    if (threadIdx.x < NN) smask[threadIdx.x] = mask[(size_t)b * NN + threadIdx.x];
    __syncthreads();

    int my = (threadIdx.x < NN) ? (smask[threadIdx.x] != 0u) : 0;
    int any = __syncthreads_or(my);
    if (!any && threadIdx.x == 0) smask[0] = 1u;
    __syncthreads();

    float* base = out + (size_t)b * NN * OO + o;

    float m = -INFINITY;
    for (int n = 0; n < NN; n++)
        if (smask[n]) m = fmaxf(m, base[(size_t)n * OO]);

    float s = 0.0f;
    for (int n = 0; n < NN; n++)
        if (smask[n]) s += __expf(base[(size_t)n * OO] - m);

    const float rs = 1.0f / s;
    for (int n = 0; n < NN; n++) {
        float v = smask[n] ? __expf(base[(size_t)n * OO] - m) * rs : 0.0f;
        base[(size_t)n * OO] = v;
    }
}

// ---------------------------------------------------------------------------
// Launch
// ---------------------------------------------------------------------------
extern "C" void kernel_launch(void* const* d_in, const int* in_sizes, int n_in,
                              void* d_out, int out_size) {
    const float*    Obs  = (const float*)d_in[0];
    const unsigned* mask = (const unsigned*)d_in[1];
    const float* g1 = (const float*)d_in[2];
    const float* b1 = (const float*)d_in[3];
    const float* W1 = (const float*)d_in[4];
    const float* g2 = (const float*)d_in[5];
    const float* b2 = (const float*)d_in[6];
    const float* W2 = (const float*)d_in[7];
    const float* g3 = (const float*)d_in[8];
    const float* b3 = (const float*)d_in[9];
    const float* W3 = (const float*)d_in[10];
    float* out = (float*)d_out;

    float *h1, *h2;
    __nv_bfloat16 *ahi, *alo, *whi, *wlo;
    cudaGetSymbolAddress((void**)&h1, g_h1);
    cudaGetSymbolAddress((void**)&h2, g_h2);
    cudaGetSymbolAddress((void**)&ahi, g_a_hi);
    cudaGetSymbolAddress((void**)&alo, g_a_lo);
    cudaGetSymbolAddress((void**)&whi, g_w_hi);
    cudaGetSymbolAddress((void**)&wlo, g_w_lo);

    static bool attr_done = false;
    const int DSMEM = 65536;
    if (!attr_done) {
        cudaFuncSetAttribute(gemm_hmma_kernel<true>,
                             cudaFuncAttributeMaxDynamicSharedMemorySize, DSMEM);
        cudaFuncSetAttribute(gemm_hmma_kernel<false>,
                             cudaFuncAttributeMaxDynamicSharedMemorySize, DSMEM);
        attr_done = true;
    }

    const dim3 gGemm(OO / 128, MROWS / 128);

    // Block 1
    ln_split_kernel<<<MROWS, 128>>>(Obs, nullptr, g1, b1, ahi, alo);
    wsplit_kernel<<<(DD * OO) / 256, 256>>>(W1, whi, wlo);
    gemm_hmma_kernel<true><<<gGemm, 256, DSMEM>>>(ahi, alo, whi, wlo, h1);

    // Block 2
    ln_split_kernel<<<MROWS, 128>>>(h1, nullptr, g2, b2, ahi, alo);
    wsplit_kernel<<<(DD * OO) / 256, 256>>>(W2, whi, wlo);
    gemm_hmma_kernel<true><<<gGemm, 256, DSMEM>>>(ahi, alo, whi, wlo, h2);

    // Block 3 (residual input h2 + h1, no activation)
    ln_split_kernel<<<MROWS, 128>>>(h2, h1, g3, b3, ahi, alo);
    wsplit_kernel<<<(DD * OO) / 256, 256>>>(W3, whi, wlo);
    gemm_hmma_kernel<false><<<gGemm, 256, DSMEM>>>(ahi, alo, whi, wlo, out);

    // Masked softmax over axis=1, in place
    softmax_kernel<<<BB, 512>>>(out, mask);
}

// round 4
// speedup vs baseline: 2.3889x; 1.0042x over previous
#include <cuda_runtime.h>
#include <cuda_bf16.h>
#include <math.h>
#include <stdint.h>

#define BB 128
#define NN 256
#define DD 512
#define OO 512
#define MROWS (BB * NN)   // 32768

// ---------------------------------------------------------------------------
// Scratch (no cudaMalloc allowed)
// ---------------------------------------------------------------------------
__device__ float g_h1[(size_t)MROWS * OO];
__device__ float g_h2[(size_t)MROWS * OO];
__device__ __nv_bfloat16 g_a_hi[(size_t)MROWS * DD];
__device__ __nv_bfloat16 g_a_lo[(size_t)MROWS * DD];
__device__ __nv_bfloat16 g_w_hi[(size_t)DD * OO];   // W^T: [N][K] bf16
__device__ __nv_bfloat16 g_w_lo[(size_t)DD * OO];

// ---------------------------------------------------------------------------
// Helpers (sm_80-era PTX only — must assemble under compute_103)
// ---------------------------------------------------------------------------
__device__ __forceinline__ uint32_t smem_to_u32(const void* p) {
    uint32_t a;
    asm("{ .reg .u64 t; cvta.to.shared.u64 t, %1; cvt.u32.u64 %0, t; }"
        : "=r"(a) : "l"(p));
    return a;
}
__device__ __forceinline__ void cp16(uint32_t dst, const void* src) {
    asm volatile("cp.async.cg.shared.global [%0], [%1], 16;"
                 :: "r"(dst), "l"(src) : "memory");
}
__device__ __forceinline__ void ldm_x4(uint32_t* r, uint32_t addr) {
    asm volatile("ldmatrix.sync.aligned.m8n8.x4.shared.b16 {%0,%1,%2,%3}, [%4];"
                 : "=r"(r[0]), "=r"(r[1]), "=r"(r[2]), "=r"(r[3]) : "r"(addr));
}
__device__ __forceinline__ void mma_bf16(float* c, const uint32_t* a,
                                         uint32_t b0, uint32_t b1) {
    asm volatile(
        "mma.sync.aligned.m16n8k16.row.col.f32.bf16.bf16.f32 "
        "{%0,%1,%2,%3}, {%4,%5,%6,%7}, {%8,%9}, {%0,%1,%2,%3};"
        : "+f"(c[0]), "+f"(c[1]), "+f"(c[2]), "+f"(c[3])
        : "r"(a[0]), "r"(a[1]), "r"(a[2]), "r"(a[3]), "r"(b0), "r"(b1));
}

// ---------------------------------------------------------------------------
// LayerNorm -> split-bf16 (hi + lo). Optional residual x2.
// ---------------------------------------------------------------------------
__global__ void ln_split_kernel(const float* __restrict__ x,
                                const float* __restrict__ x2,
                                const float* __restrict__ g,
                                const float* __restrict__ b,
                                __nv_bfloat16* __restrict__ yhi,
                                __nv_bfloat16* __restrict__ ylo) {
    const int row = blockIdx.x;
    const int tid = threadIdx.x;

    float4 v = reinterpret_cast<const float4*>(x + (size_t)row * DD)[tid];
    if (x2 != nullptr) {
        float4 v2 = reinterpret_cast<const float4*>(x2 + (size_t)row * DD)[tid];
        v.x += v2.x; v.y += v2.y; v.z += v2.z; v.w += v2.w;
    }

    float s  = v.x + v.y + v.z + v.w;
    float ss = v.x * v.x + v.y * v.y + v.z * v.z + v.w * v.w;
    #pragma unroll
    for (int o = 16; o > 0; o >>= 1) {
        s  += __shfl_xor_sync(0xFFFFFFFFu, s,  o);
        ss += __shfl_xor_sync(0xFFFFFFFFu, ss, o);
    }
    __shared__ float sh_s[4], sh_ss[4];
    const int w = tid >> 5;
    if ((tid & 31) == 0) { sh_s[w] = s; sh_ss[w] = ss; }
    __syncthreads();
    s  = sh_s[0] + sh_s[1] + sh_s[2] + sh_s[3];
    ss = sh_ss[0] + sh_ss[1] + sh_ss[2] + sh_ss[3];

    const float mean = s * (1.0f / DD);
    const float var  = ss * (1.0f / DD) - mean * mean;
    const float r    = rsqrtf(var + 1e-5f);

    const float4 gv = reinterpret_cast<const float4*>(g)[tid];
    const float4 bv = reinterpret_cast<const float4*>(b)[tid];
    float o0 = (v.x - mean) * r * gv.x + bv.x;
    float o1 = (v.y - mean) * r * gv.y + bv.y;
    float o2 = (v.z - mean) * r * gv.z + bv.z;
    float o3 = (v.w - mean) * r * gv.w + bv.w;

    __nv_bfloat16 h0 = __float2bfloat16(o0), h1 = __float2bfloat16(o1);
    __nv_bfloat16 h2 = __float2bfloat16(o2), h3 = __float2bfloat16(o3);
    __nv_bfloat16 l0 = __float2bfloat16(o0 - __bfloat162float(h0));
    __nv_bfloat16 l1 = __float2bfloat16(o1 - __bfloat162float(h1));
    __nv_bfloat16 l2 = __float2bfloat16(o2 - __bfloat162float(h2));
    __nv_bfloat16 l3 = __float2bfloat16(o3 - __bfloat162float(h3));

    __nv_bfloat162* ph = reinterpret_cast<__nv_bfloat162*>(yhi + (size_t)row * DD);
    __nv_bfloat162* pl = reinterpret_cast<__nv_bfloat162*>(ylo + (size_t)row * DD);
    ph[tid * 2]     = __nv_bfloat162(h0, h1);
    ph[tid * 2 + 1] = __nv_bfloat162(h2, h3);
    pl[tid * 2]     = __nv_bfloat162(l0, l1);
    pl[tid * 2 + 1] = __nv_bfloat162(l2, l3);
}

// ---------------------------------------------------------------------------
// Weight split+transpose: W[K,N] f32 -> Wt_hi/Wt_lo [N,K] bf16
// ---------------------------------------------------------------------------
__global__ void wsplit_kernel(const float* __restrict__ W,
                              __nv_bfloat16* __restrict__ hi,
                              __nv_bfloat16* __restrict__ lo) {
    int idx = blockIdx.x * 256 + threadIdx.x;
    int k = idx >> 9, n = idx & 511;
    float w = W[idx];
    __nv_bfloat16 h = __float2bfloat16(w);
    hi[(size_t)n * DD + k] = h;
    lo[(size_t)n * DD + k] = __float2bfloat16(w - __bfloat162float(h));
}

// ---------------------------------------------------------------------------
// Split-bf16 HMMA GEMM with ldmatrix fragment loads.
// C[M,N] = (Ahi+Alo)[M,K] @ (Bhi+Blo)^T, B in [N,K].
// CTA 128x128, BK=32, 2-stage cp.async double buffer, 8 warps (32x64 each).
// SMEM tile layout per array/stage: 128 rows x 64B, 16B chunks XOR-swizzled:
//   byte(row, k) = row*64 + (((k>>3) ^ (row&3)) & 3)*16 + (k&7)*2
// ---------------------------------------------------------------------------
template <bool TANH>
__global__ __launch_bounds__(256, 2)
void gemm_hmma_kernel(const __nv_bfloat16* __restrict__ Ahi,
                      const __nv_bfloat16* __restrict__ Alo,
                      const __nv_bfloat16* __restrict__ Bhi,
                      const __nv_bfloat16* __restrict__ Blo,
                      float* __restrict__ C) {
    extern __shared__ char smem[];
    const uint32_t sb = smem_to_u32(smem);
    const uint32_t SA_H = sb;
    const uint32_t SA_L = sb + 16384;
    const uint32_t SB_H = sb + 32768;
    const uint32_t SB_L = sb + 49152;

    const int tid  = threadIdx.x;
    const int lane = tid & 31;
    const int wid  = tid >> 5;
    const int m0 = blockIdx.y * 128;
    const int n0 = blockIdx.x * 128;
    const int warp_m = (wid >> 1) * 32;   // 0,32,64,96
    const int warp_n = (wid & 1) * 64;    // 0,64

    float acc[2][8][4];
    #pragma unroll
    for (int i = 0; i < 2; i++)
        #pragma unroll
        for (int j = 0; j < 8; j++)
            #pragma unroll
            for (int q = 0; q < 4; q++) acc[i][j][q] = 0.0f;

    // --- ldmatrix per-lane base addressing (precomputed) ---
    // A x4 tiles (mt,kb): t0=(r0..7,kb) t1=(r8..15,kb) t2=(r0..7,kb+8) t3=(r8..15,kb+8)
    const int arow  = warp_m + (lane & 7) + ((lane >> 3) & 1) * 8;  // + mt*16
    const int akblk = (lane >> 4) & 1;                              // k-chunk bias
    const int ax    = arow & 3;
    // B x4 tiles (jj,kb): t0=(n0..7,kb) t1=(n0..7,kb+8) t2=(n8..15,kb) t3=(n8..15,kb+8)
    const int brow  = warp_n + (lane & 7) + ((lane >> 4) & 1) * 8;  // + jj*16
    const int bkblk = (lane >> 3) & 1;
    const int bx    = brow & 3;

    #define AOFF(mt, kb) \
        (uint32_t)((arow + (mt) * 16) * 64 + (((((kb) >> 3) + akblk) ^ ax) & 3) * 16)
    #define BOFF(jj, kb) \
        (uint32_t)((brow + (jj) * 16) * 64 + (((((kb) >> 3) + bkblk) ^ bx) & 3) * 16)

    // --- cp.async stage load: 2 x 16B per array per thread ---
    const int c0row = tid >> 2,          c0ch = tid & 3;
    const int c1row = (tid + 256) >> 2;
    const uint32_t d0 = (uint32_t)(c0row * 64 + ((c0ch ^ (c0row & 3)) << 4));
    const uint32_t d1 = (uint32_t)(c1row * 64 + ((c0ch ^ (c1row & 3)) << 4));
    const size_t gA0 = (size_t)(m0 + c0row) * DD + c0ch * 8;
    const size_t gA1 = (size_t)(m0 + c1row) * DD + c0ch * 8;
    const size_t gB0 = (size_t)(n0 + c0row) * DD + c0ch * 8;
    const size_t gB1 = (size_t)(n0 + c1row) * DD + c0ch * 8;

    #define LOAD_STAGE(it, buf) do {                                     \
        const int _k0 = (it) * 32;                                       \
        const uint32_t _so = (uint32_t)(buf) * 8192u;                    \
        cp16(SA_H + _so + d0, Ahi + gA0 + _k0);                          \
        cp16(SA_H + _so + d1, Ahi + gA1 + _k0);                          \
        cp16(SA_L + _so + d0, Alo + gA0 + _k0);                          \
        cp16(SA_L + _so + d1, Alo + gA1 + _k0);                          \
        cp16(SB_H + _so + d0, Bhi + gB0 + _k0);                          \
        cp16(SB_H + _so + d1, Bhi + gB1 + _k0);                          \
        cp16(SB_L + _so + d0, Blo + gB0 + _k0);                          \
        cp16(SB_L + _so + d1, Blo + gB1 + _k0);                          \
        asm volatile("cp.async.commit_group;" ::: "memory");             \
    } while (0)

    LOAD_STAGE(0, 0);

    const int NK = DD / 32;   // 16
    for (int it = 0; it < NK; it++) {
        if (it + 1 < NK) {
            LOAD_STAGE(it + 1, (it + 1) & 1);
            asm volatile("cp.async.wait_group 1;" ::: "memory");
        } else {
            asm volatile("cp.async.wait_group 0;" ::: "memory");
        }
        __syncthreads();

        const uint32_t so = (uint32_t)(it & 1) * 8192u;
        #pragma unroll
        for (int ks = 0; ks < 2; ks++) {
            const int kb = ks * 16;
            // A fragments (hi, lo) for both m16 tiles: 4 ldmatrix.x4
            uint32_t ah[2][4], al[2][4];
            #pragma unroll
            for (int mt = 0; mt < 2; mt++) {
                ldm_x4(ah[mt], SA_H + so + AOFF(mt, kb));
                ldm_x4(al[mt], SA_L + so + AOFF(mt, kb));
            }
            // B fragments: 4+4 ldmatrix.x4 -> bq[jj][0,1]=j(2jj), [2,3]=j(2jj+1)
            uint32_t bh[4][4], bl[4][4];
            #pragma unroll
            for (int jj = 0; jj < 4; jj++) {
                ldm_x4(bh[jj], SB_H + so + BOFF(jj, kb));
                ldm_x4(bl[jj], SB_L + so + BOFF(jj, kb));
            }
            #pragma unroll
            for (int j = 0; j < 8; j++) {
                const int jj = j >> 1, jh = (j & 1) * 2;
                const uint32_t bh0 = bh[jj][jh], bh1 = bh[jj][jh + 1];
                const uint32_t bl0 = bl[jj][jh], bl1 = bl[jj][jh + 1];
                #pragma unroll
                for (int mt = 0; mt < 2; mt++) {
                    mma_bf16(acc[mt][j], ah[mt], bh0, bh1);
                    mma_bf16(acc[mt][j], ah[mt], bl0, bl1);
                    mma_bf16(acc[mt][j], al[mt], bh0, bh1);
                }
            }
        }
        __syncthreads();
    }
    #undef LOAD_STAGE
    #undef AOFF
    #undef BOFF

    // Epilogue: direct global float2 stores
    #pragma unroll
    for (int mt = 0; mt < 2; mt++) {
        const int row = m0 + warp_m + mt * 16 + (lane >> 2);
        #pragma unroll
        for (int j = 0; j < 8; j++) {
            const int col = n0 + warp_n + j * 8 + (lane & 3) * 2;
            float v0 = acc[mt][j][0], v1 = acc[mt][j][1];
            float v2 = acc[mt][j][2], v3 = acc[mt][j][3];
            if (TANH) { v0 = tanhf(v0); v1 = tanhf(v1); v2 = tanhf(v2); v3 = tanhf(v3); }
            *reinterpret_cast<float2*>(C + (size_t)row * OO + col)       = make_float2(v0, v1);
            *reinterpret_cast<float2*>(C + (size_t)(row + 8) * OO + col) = make_float2(v2, v3);
        }
    }
}

// ---------------------------------------------------------------------------
// Masked softmax over axis=1 (N=256), in-place on out[B, N, O].
// ---------------------------------------------------------------------------
__global__ __launch_bounds__(512)
void softmax_kernel(float* __restrict__ out, const unsigned* __restrict__ mask) {
    const int b = blockIdx.x;
    const int o = threadIdx.x;

    __shared__ unsigned smask[NN];
    if (threadIdx.x < NN) smask[threadIdx.x] = mask[(size_t)b * NN + threadIdx.x];
    __syncthreads();

    int my = (threadIdx.x < NN) ? (smask[threadIdx.x] != 0u) : 0;
    int any = __syncthreads_or(my);
    if (!any && threadIdx.x == 0) smask[0] = 1u;
    __syncthreads();

    float* base = out + (size_t)b * NN * OO + o;

    float m = -INFINITY;
    for (int n = 0; n < NN; n++)
        if (smask[n]) m = fmaxf(m, base[(size_t)n * OO]);

    float s = 0.0f;
    for (int n = 0; n < NN; n++)
        if (smask[n]) s += __expf(base[(size_t)n * OO] - m);

    const float rs = 1.0f / s;
    for (int n = 0; n < NN; n++) {
        float v = smask[n] ? __expf(base[(size_t)n * OO] - m) * rs : 0.0f;
        base[(size_t)n * OO] = v;
    }
}

// ---------------------------------------------------------------------------
// Launch
// ---------------------------------------------------------------------------
extern "C" void kernel_launch(void* const* d_in, const int* in_sizes, int n_in,
                              void* d_out, int out_size) {
    const float*    Obs  = (const float*)d_in[0];
    const unsigned* mask = (const unsigned*)d_in[1];
    const float* g1 = (const float*)d_in[2];
    const float* b1 = (const float*)d_in[3];
    const float* W1 = (const float*)d_in[4];
    const float* g2 = (const float*)d_in[5];
    const float* b2 = (const float*)d_in[6];
    const float* W2 = (const float*)d_in[7];
    const float* g3 = (const float*)d_in[8];
    const float* b3 = (const float*)d_in[9];
    const float* W3 = (const float*)d_in[10];
    float* out = (float*)d_out;

    float *h1, *h2;
    __nv_bfloat16 *ahi, *alo, *whi, *wlo;
    cudaGetSymbolAddress((void**)&h1, g_h1);
    cudaGetSymbolAddress((void**)&h2, g_h2);
    cudaGetSymbolAddress((void**)&ahi, g_a_hi);
    cudaGetSymbolAddress((void**)&alo, g_a_lo);
    cudaGetSymbolAddress((void**)&whi, g_w_hi);
    cudaGetSymbolAddress((void**)&wlo, g_w_lo);

    static bool attr_done = false;
    const int DSMEM = 65536;
    if (!attr_done) {
        cudaFuncSetAttribute(gemm_hmma_kernel<true>,
                             cudaFuncAttributeMaxDynamicSharedMemorySize, DSMEM);
        cudaFuncSetAttribute(gemm_hmma_kernel<false>,
                             cudaFuncAttributeMaxDynamicSharedMemorySize, DSMEM);
        attr_done = true;
    }

    const dim3 gGemm(OO / 128, MROWS / 128);

    // Block 1
    ln_split_kernel<<<MROWS, 128>>>(Obs, nullptr, g1, b1, ahi, alo);
    wsplit_kernel<<<(DD * OO) / 256, 256>>>(W1, whi, wlo);
    gemm_hmma_kernel<true><<<gGemm, 256, DSMEM>>>(ahi, alo, whi, wlo, h1);

    // Block 2
    ln_split_kernel<<<MROWS, 128>>>(h1, nullptr, g2, b2, ahi, alo);
    wsplit_kernel<<<(DD * OO) / 256, 256>>>(W2, whi, wlo);
    gemm_hmma_kernel<true><<<gGemm, 256, DSMEM>>>(ahi, alo, whi, wlo, h2);

    // Block 3 (residual input h2 + h1, no activation)
    ln_split_kernel<<<MROWS, 128>>>(h2, h1, g3, b3, ahi, alo);
    wsplit_kernel<<<(DD * OO) / 256, 256>>>(W3, whi, wlo);
    gemm_hmma_kernel<false><<<gGemm, 256, DSMEM>>>(ahi, alo, whi, wlo, out);

    // Masked softmax over axis=1, in place
    softmax_kernel<<<BB, 512>>>(out, mask);
}

// round 5
// speedup vs baseline: 3.0628x; 1.2821x over previous
#include <cuda_runtime.h>
#include <cuda_fp16.h>
#include <math.h>
#include <stdint.h>

#define BB 128
#define NN 256
#define DD 512
#define OO 512
#define MROWS (BB * NN)   // 32768

// ---------------------------------------------------------------------------
// Scratch (no cudaMalloc allowed)
// ---------------------------------------------------------------------------
__device__ float g_h1[(size_t)MROWS * OO];
__device__ float g_h2[(size_t)MROWS * OO];
__device__ __half g_a_hi[(size_t)MROWS * DD];
__device__ __half g_a_lo[(size_t)MROWS * DD];
__device__ __half g_w_hi[(size_t)DD * OO];   // W^T: [N][K] fp16

// ---------------------------------------------------------------------------
// Helpers (sm_80-era PTX only — must assemble under compute_103)
// ---------------------------------------------------------------------------
__device__ __forceinline__ uint32_t smem_to_u32(const void* p) {
    uint32_t a;
    asm("{ .reg .u64 t; cvta.to.shared.u64 t, %1; cvt.u32.u64 %0, t; }"
        : "=r"(a) : "l"(p));
    return a;
}
__device__ __forceinline__ void cp16(uint32_t dst, const void* src) {
    asm volatile("cp.async.cg.shared.global [%0], [%1], 16;"
                 :: "r"(dst), "l"(src) : "memory");
}
__device__ __forceinline__ void ldm_x4(uint32_t* r, uint32_t addr) {
    asm volatile("ldmatrix.sync.aligned.m8n8.x4.shared.b16 {%0,%1,%2,%3}, [%4];"
                 : "=r"(r[0]), "=r"(r[1]), "=r"(r[2]), "=r"(r[3]) : "r"(addr));
}
__device__ __forceinline__ void mma_fp16(float* c, const uint32_t* a,
                                         uint32_t b0, uint32_t b1) {
    asm volatile(
        "mma.sync.aligned.m16n8k16.row.col.f32.f16.f16.f32 "
        "{%0,%1,%2,%3}, {%4,%5,%6,%7}, {%8,%9}, {%0,%1,%2,%3};"
        : "+f"(c[0]), "+f"(c[1]), "+f"(c[2]), "+f"(c[3])
        : "r"(a[0]), "r"(a[1]), "r"(a[2]), "r"(a[3]), "r"(b0), "r"(b1));
}

// ---------------------------------------------------------------------------
// LayerNorm -> split-fp16 (hi + lo). Optional residual x2.
// ---------------------------------------------------------------------------
__global__ void ln_split_kernel(const float* __restrict__ x,
                                const float* __restrict__ x2,
                                const float* __restrict__ g,
                                const float* __restrict__ b,
                                __half* __restrict__ yhi,
                                __half* __restrict__ ylo) {
    const int row = blockIdx.x;
    const int tid = threadIdx.x;

    float4 v = reinterpret_cast<const float4*>(x + (size_t)row * DD)[tid];
    if (x2 != nullptr) {
        float4 v2 = reinterpret_cast<const float4*>(x2 + (size_t)row * DD)[tid];
        v.x += v2.x; v.y += v2.y; v.z += v2.z; v.w += v2.w;
    }

    float s  = v.x + v.y + v.z + v.w;
    float ss = v.x * v.x + v.y * v.y + v.z * v.z + v.w * v.w;
    #pragma unroll
    for (int o = 16; o > 0; o >>= 1) {
        s  += __shfl_xor_sync(0xFFFFFFFFu, s,  o);
        ss += __shfl_xor_sync(0xFFFFFFFFu, ss, o);
    }
    __shared__ float sh_s[4], sh_ss[4];
    const int w = tid >> 5;
    if ((tid & 31) == 0) { sh_s[w] = s; sh_ss[w] = ss; }
    __syncthreads();
    s  = sh_s[0] + sh_s[1] + sh_s[2] + sh_s[3];
    ss = sh_ss[0] + sh_ss[1] + sh_ss[2] + sh_ss[3];

    const float mean = s * (1.0f / DD);
    const float var  = ss * (1.0f / DD) - mean * mean;
    const float r    = rsqrtf(var + 1e-5f);

    const float4 gv = reinterpret_cast<const float4*>(g)[tid];
    const float4 bv = reinterpret_cast<const float4*>(b)[tid];
    float o0 = (v.x - mean) * r * gv.x + bv.x;
    float o1 = (v.y - mean) * r * gv.y + bv.y;
    float o2 = (v.z - mean) * r * gv.z + bv.z;
    float o3 = (v.w - mean) * r * gv.w + bv.w;

    __half h0 = __float2half_rn(o0), h1 = __float2half_rn(o1);
    __half h2 = __float2half_rn(o2), h3 = __float2half_rn(o3);
    __half l0 = __float2half_rn(o0 - __half2float(h0));
    __half l1 = __float2half_rn(o1 - __half2float(h1));
    __half l2 = __float2half_rn(o2 - __half2float(h2));
    __half l3 = __float2half_rn(o3 - __half2float(h3));

    __half2* ph = reinterpret_cast<__half2*>(yhi + (size_t)row * DD);
    __half2* pl = reinterpret_cast<__half2*>(ylo + (size_t)row * DD);
    ph[tid * 2]     = __halves2half2(h0, h1);
    ph[tid * 2 + 1] = __halves2half2(h2, h3);
    pl[tid * 2]     = __halves2half2(l0, l1);
    pl[tid * 2 + 1] = __halves2half2(l2, l3);
}

// ---------------------------------------------------------------------------
// Weight convert+transpose: W[K,N] f32 -> Wt [N,K] fp16
// ---------------------------------------------------------------------------
__global__ void wsplit_kernel(const float* __restrict__ W,
                              __half* __restrict__ hi) {
    int idx = blockIdx.x * 256 + threadIdx.x;
    int k = idx >> 9, n = idx & 511;
    hi[(size_t)n * DD + k] = __float2half_rn(W[idx]);
}

// ---------------------------------------------------------------------------
// Split-fp16 HMMA GEMM: C[M,N] = (Ahi+Alo)[M,K] @ B^T, B in [N,K] fp16.
// CTA 128x128, BK=32, 2-stage cp.async double buffer, 8 warps (32x64 each).
// SMEM tile layout per array/stage: 128 rows x 64B, 16B chunks XOR-swizzled:
//   byte(row, k) = row*64 + (((k>>3) ^ (row&3)) & 3)*16 + (k&7)*2
// ---------------------------------------------------------------------------
template <bool TANH>
__global__ __launch_bounds__(256, 2)
void gemm_hmma_kernel(const __half* __restrict__ Ahi,
                      const __half* __restrict__ Alo,
                      const __half* __restrict__ Bhi,
                      float* __restrict__ C) {
    extern __shared__ char smem[];
    const uint32_t sb = smem_to_u32(smem);
    const uint32_t SA_H = sb;
    const uint32_t SA_L = sb + 16384;
    const uint32_t SB_H = sb + 32768;

    const int tid  = threadIdx.x;
    const int lane = tid & 31;
    const int wid  = tid >> 5;
    const int m0 = blockIdx.y * 128;
    const int n0 = blockIdx.x * 128;
    const int warp_m = (wid >> 1) * 32;   // 0,32,64,96
    const int warp_n = (wid & 1) * 64;    // 0,64

    float acc[2][8][4];
    #pragma unroll
    for (int i = 0; i < 2; i++)
        #pragma unroll
        for (int j = 0; j < 8; j++)
            #pragma unroll
            for (int q = 0; q < 4; q++) acc[i][j][q] = 0.0f;

    // --- ldmatrix per-lane base addressing ---
    const int arow  = warp_m + (lane & 7) + ((lane >> 3) & 1) * 8;  // + mt*16
    const int akblk = (lane >> 4) & 1;
    const int ax    = arow & 3;
    const int brow  = warp_n + (lane & 7) + ((lane >> 4) & 1) * 8;  // + jj*16
    const int bkblk = (lane >> 3) & 1;
    const int bx    = brow & 3;

    #define AOFF(mt, kb) \
        (uint32_t)((arow + (mt) * 16) * 64 + (((((kb) >> 3) + akblk) ^ ax) & 3) * 16)
    #define BOFF(jj, kb) \
        (uint32_t)((brow + (jj) * 16) * 64 + (((((kb) >> 3) + bkblk) ^ bx) & 3) * 16)

    // --- cp.async stage load: 2 x 16B per array per thread (6 cp.async) ---
    const int c0row = tid >> 2,          c0ch = tid & 3;
    const int c1row = (tid + 256) >> 2;
    const uint32_t d0 = (uint32_t)(c0row * 64 + ((c0ch ^ (c0row & 3)) << 4));
    const uint32_t d1 = (uint32_t)(c1row * 64 + ((c0ch ^ (c1row & 3)) << 4));
    const size_t gA0 = (size_t)(m0 + c0row) * DD + c0ch * 8;
    const size_t gA1 = (size_t)(m0 + c1row) * DD + c0ch * 8;
    const size_t gB0 = (size_t)(n0 + c0row) * DD + c0ch * 8;
    const size_t gB1 = (size_t)(n0 + c1row) * DD + c0ch * 8;

    #define LOAD_STAGE(it, buf) do {                                     \
        const int _k0 = (it) * 32;                                       \
        const uint32_t _so = (uint32_t)(buf) * 8192u;                    \
        cp16(SA_H + _so + d0, Ahi + gA0 + _k0);                          \
        cp16(SA_H + _so + d1, Ahi + gA1 + _k0);                          \
        cp16(SA_L + _so + d0, Alo + gA0 + _k0);                          \
        cp16(SA_L + _so + d1, Alo + gA1 + _k0);                          \
        cp16(SB_H + _so + d0, Bhi + gB0 + _k0);                          \
        cp16(SB_H + _so + d1, Bhi + gB1 + _k0);                          \
        asm volatile("cp.async.commit_group;" ::: "memory");             \
    } while (0)

    LOAD_STAGE(0, 0);

    const int NK = DD / 32;   // 16
    for (int it = 0; it < NK; it++) {
        if (it + 1 < NK) {
            LOAD_STAGE(it + 1, (it + 1) & 1);
            asm volatile("cp.async.wait_group 1;" ::: "memory");
        } else {
            asm volatile("cp.async.wait_group 0;" ::: "memory");
        }
        __syncthreads();

        const uint32_t so = (uint32_t)(it & 1) * 8192u;
        #pragma unroll
        for (int ks = 0; ks < 2; ks++) {
            const int kb = ks * 16;
            uint32_t ah[2][4], al[2][4];
            #pragma unroll
            for (int mt = 0; mt < 2; mt++) {
                ldm_x4(ah[mt], SA_H + so + AOFF(mt, kb));
                ldm_x4(al[mt], SA_L + so + AOFF(mt, kb));
            }
            uint32_t bh[4][4];
            #pragma unroll
            for (int jj = 0; jj < 4; jj++)
                ldm_x4(bh[jj], SB_H + so + BOFF(jj, kb));
            #pragma unroll
            for (int j = 0; j < 8; j++) {
                const int jj = j >> 1, jh = (j & 1) * 2;
                const uint32_t b0 = bh[jj][jh], b1 = bh[jj][jh + 1];
                #pragma unroll
                for (int mt = 0; mt < 2; mt++) {
                    mma_fp16(acc[mt][j], ah[mt], b0, b1);
                    mma_fp16(acc[mt][j], al[mt], b0, b1);
                }
            }
        }
        __syncthreads();
    }
    #undef LOAD_STAGE
    #undef AOFF
    #undef BOFF

    // Epilogue: direct global float2 stores
    #pragma unroll
    for (int mt = 0; mt < 2; mt++) {
        const int row = m0 + warp_m + mt * 16 + (lane >> 2);
        #pragma unroll
        for (int j = 0; j < 8; j++) {
            const int col = n0 + warp_n + j * 8 + (lane & 3) * 2;
            float v0 = acc[mt][j][0], v1 = acc[mt][j][1];
            float v2 = acc[mt][j][2], v3 = acc[mt][j][3];
            if (TANH) { v0 = tanhf(v0); v1 = tanhf(v1); v2 = tanhf(v2); v3 = tanhf(v3); }
            *reinterpret_cast<float2*>(C + (size_t)row * OO + col)       = make_float2(v0, v1);
            *reinterpret_cast<float2*>(C + (size_t)(row + 8) * OO + col) = make_float2(v2, v3);
        }
    }
}

// ---------------------------------------------------------------------------
// Masked softmax over axis=1 (N=256), in-place on out[B, N, O].
// ---------------------------------------------------------------------------
__global__ __launch_bounds__(512)
void softmax_kernel(float* __restrict__ out, const unsigned* __restrict__ mask) {
    const int b = blockIdx.x;
    const int o = threadIdx.x;

    __shared__ unsigned smask[NN];
    if (threadIdx.x < NN) smask[threadIdx.x] = mask[(size_t)b * NN + threadIdx.x];
    __syncthreads();

    int my = (threadIdx.x < NN) ? (smask[threadIdx.x] != 0u) : 0;
    int any = __syncthreads_or(my);
    if (!any && threadIdx.x == 0) smask[0] = 1u;
    __syncthreads();

    float* base = out + (size_t)b * NN * OO + o;

    float m = -INFINITY;
    for (int n = 0; n < NN; n++)
        if (smask[n]) m = fmaxf(m, base[(size_t)n * OO]);

    float s = 0.0f;
    for (int n = 0; n < NN; n++)
        if (smask[n]) s += __expf(base[(size_t)n * OO] - m);

    const float rs = 1.0f / s;
    for (int n = 0; n < NN; n++) {
        float v = smask[n] ? __expf(base[(size_t)n * OO] - m) * rs : 0.0f;
        base[(size_t)n * OO] = v;
    }
}

// ---------------------------------------------------------------------------
// Launch
// ---------------------------------------------------------------------------
extern "C" void kernel_launch(void* const* d_in, const int* in_sizes, int n_in,
                              void* d_out, int out_size) {
    const float*    Obs  = (const float*)d_in[0];
    const unsigned* mask = (const unsigned*)d_in[1];
    const float* g1 = (const float*)d_in[2];
    const float* b1 = (const float*)d_in[3];
    const float* W1 = (const float*)d_in[4];
    const float* g2 = (const float*)d_in[5];
    const float* b2 = (const float*)d_in[6];
    const float* W2 = (const float*)d_in[7];
    const float* g3 = (const float*)d_in[8];
    const float* b3 = (const float*)d_in[9];
    const float* W3 = (const float*)d_in[10];
    float* out = (float*)d_out;

    float *h1, *h2;
    __half *ahi, *alo, *whi;
    cudaGetSymbolAddress((void**)&h1, g_h1);
    cudaGetSymbolAddress((void**)&h2, g_h2);
    cudaGetSymbolAddress((void**)&ahi, g_a_hi);
    cudaGetSymbolAddress((void**)&alo, g_a_lo);
    cudaGetSymbolAddress((void**)&whi, g_w_hi);

    static bool attr_done = false;
    const int DSMEM = 49152;   // 3 arrays x 2 stages x 8192
    if (!attr_done) {
        cudaFuncSetAttribute(gemm_hmma_kernel<true>,
                             cudaFuncAttributeMaxDynamicSharedMemorySize, DSMEM);
        cudaFuncSetAttribute(gemm_hmma_kernel<false>,
                             cudaFuncAttributeMaxDynamicSharedMemorySize, DSMEM);
        attr_done = true;
    }

    const dim3 gGemm(OO / 128, MROWS / 128);

    // Block 1
    ln_split_kernel<<<MROWS, 128>>>(Obs, nullptr, g1, b1, ahi, alo);
    wsplit_kernel<<<(DD * OO) / 256, 256>>>(W1, whi);
    gemm_hmma_kernel<true><<<gGemm, 256, DSMEM>>>(ahi, alo, whi, h1);

    // Block 2
    ln_split_kernel<<<MROWS, 128>>>(h1, nullptr, g2, b2, ahi, alo);
    wsplit_kernel<<<(DD * OO) / 256, 256>>>(W2, whi);
    gemm_hmma_kernel<true><<<gGemm, 256, DSMEM>>>(ahi, alo, whi, h2);

    // Block 3 (residual input h2 + h1, no activation)
    ln_split_kernel<<<MROWS, 128>>>(h2, h1, g3, b3, ahi, alo);
    wsplit_kernel<<<(DD * OO) / 256, 256>>>(W3, whi);
    gemm_hmma_kernel<false><<<gGemm, 256, DSMEM>>>(ahi, alo, whi, out);

    // Masked softmax over axis=1, in place
    softmax_kernel<<<BB, 512>>>(out, mask);
}

// round 6
// speedup vs baseline: 3.6856x; 1.2033x over previous
#include <cuda_runtime.h>
#include <cuda_fp16.h>
#include <math.h>
#include <stdint.h>

#define BB 128
#define NN 256
#define DD 512
#define OO 512
#define MROWS (BB * NN)   // 32768

// ---------------------------------------------------------------------------
// Scratch (no cudaMalloc allowed)
// ---------------------------------------------------------------------------
__device__ float g_h1[(size_t)MROWS * OO];
__device__ float g_h2[(size_t)MROWS * OO];
__device__ __half g_a[(size_t)MROWS * DD];
__device__ __half g_w[(size_t)DD * OO];   // W^T: [N][K] fp16

// ---------------------------------------------------------------------------
// Helpers (sm_80-era PTX only — must assemble under compute_103)
// ---------------------------------------------------------------------------
__device__ __forceinline__ uint32_t smem_to_u32(const void* p) {
    uint32_t a;
    asm("{ .reg .u64 t; cvta.to.shared.u64 t, %1; cvt.u32.u64 %0, t; }"
        : "=r"(a) : "l"(p));
    return a;
}
__device__ __forceinline__ void cp16(uint32_t dst, const void* src) {
    asm volatile("cp.async.cg.shared.global [%0], [%1], 16;"
                 :: "r"(dst), "l"(src) : "memory");
}
__device__ __forceinline__ void ldm_x4(uint32_t* r, uint32_t addr) {
    asm volatile("ldmatrix.sync.aligned.m8n8.x4.shared.b16 {%0,%1,%2,%3}, [%4];"
                 : "=r"(r[0]), "=r"(r[1]), "=r"(r[2]), "=r"(r[3]) : "r"(addr));
}
__device__ __forceinline__ void mma_fp16(float* c, const uint32_t* a,
                                         uint32_t b0, uint32_t b1) {
    asm volatile(
        "mma.sync.aligned.m16n8k16.row.col.f32.f16.f16.f32 "
        "{%0,%1,%2,%3}, {%4,%5,%6,%7}, {%8,%9}, {%0,%1,%2,%3};"
        : "+f"(c[0]), "+f"(c[1]), "+f"(c[2]), "+f"(c[3])
        : "r"(a[0]), "r"(a[1]), "r"(a[2]), "r"(a[3]), "r"(b0), "r"(b1));
}

// ---------------------------------------------------------------------------
// LayerNorm -> fp16. Optional residual x2.
// ---------------------------------------------------------------------------
__global__ void ln_fp16_kernel(const float* __restrict__ x,
                               const float* __restrict__ x2,
                               const float* __restrict__ g,
                               const float* __restrict__ b,
                               __half* __restrict__ y) {
    const int row = blockIdx.x;
    const int tid = threadIdx.x;

    float4 v = reinterpret_cast<const float4*>(x + (size_t)row * DD)[tid];
    if (x2 != nullptr) {
        float4 v2 = reinterpret_cast<const float4*>(x2 + (size_t)row * DD)[tid];
        v.x += v2.x; v.y += v2.y; v.z += v2.z; v.w += v2.w;
    }

    float s  = v.x + v.y + v.z + v.w;
    float ss = v.x * v.x + v.y * v.y + v.z * v.z + v.w * v.w;
    #pragma unroll
    for (int o = 16; o > 0; o >>= 1) {
        s  += __shfl_xor_sync(0xFFFFFFFFu, s,  o);
        ss += __shfl_xor_sync(0xFFFFFFFFu, ss, o);
    }
    __shared__ float sh_s[4], sh_ss[4];
    const int w = tid >> 5;
    if ((tid & 31) == 0) { sh_s[w] = s; sh_ss[w] = ss; }
    __syncthreads();
    s  = sh_s[0] + sh_s[1] + sh_s[2] + sh_s[3];
    ss = sh_ss[0] + sh_ss[1] + sh_ss[2] + sh_ss[3];

    const float mean = s * (1.0f / DD);
    const float var  = ss * (1.0f / DD) - mean * mean;
    const float r    = rsqrtf(var + 1e-5f);

    const float4 gv = reinterpret_cast<const float4*>(g)[tid];
    const float4 bv = reinterpret_cast<const float4*>(b)[tid];
    float o0 = (v.x - mean) * r * gv.x + bv.x;
    float o1 = (v.y - mean) * r * gv.y + bv.y;
    float o2 = (v.z - mean) * r * gv.z + bv.z;
    float o3 = (v.w - mean) * r * gv.w + bv.w;

    __half2* ph = reinterpret_cast<__half2*>(y + (size_t)row * DD);
    ph[tid * 2]     = __halves2half2(__float2half_rn(o0), __float2half_rn(o1));
    ph[tid * 2 + 1] = __halves2half2(__float2half_rn(o2), __float2half_rn(o3));
}

// ---------------------------------------------------------------------------
// Weight convert+transpose: W[K,N] f32 -> Wt [N,K] fp16
// ---------------------------------------------------------------------------
__global__ void wconv_kernel(const float* __restrict__ W,
                             __half* __restrict__ o) {
    int idx = blockIdx.x * 256 + threadIdx.x;
    int k = idx >> 9, n = idx & 511;
    o[(size_t)n * DD + k] = __float2half_rn(W[idx]);
}

// ---------------------------------------------------------------------------
// fp16 HMMA GEMM: C[M,N] = A[M,K] @ B^T, B in [N,K] fp16.
// CTA 128x128, BK=32, 2-stage cp.async double buffer, 8 warps (32x64 each).
// SMEM tile layout per array/stage: 128 rows x 64B, 16B chunks XOR-swizzled:
//   byte(row, k) = row*64 + (((k>>3) ^ (row&3)) & 3)*16 + (k&7)*2
// ---------------------------------------------------------------------------
template <bool TANH>
__global__ __launch_bounds__(256, 2)
void gemm_hmma_kernel(const __half* __restrict__ A,
                      const __half* __restrict__ B,
                      float* __restrict__ C) {
    extern __shared__ char smem[];
    const uint32_t sb = smem_to_u32(smem);
    const uint32_t SA = sb;
    const uint32_t SB = sb + 16384;

    const int tid  = threadIdx.x;
    const int lane = tid & 31;
    const int wid  = tid >> 5;
    const int m0 = blockIdx.y * 128;
    const int n0 = blockIdx.x * 128;
    const int warp_m = (wid >> 1) * 32;   // 0,32,64,96
    const int warp_n = (wid & 1) * 64;    // 0,64

    float acc[2][8][4];
    #pragma unroll
    for (int i = 0; i < 2; i++)
        #pragma unroll
        for (int j = 0; j < 8; j++)
            #pragma unroll
            for (int q = 0; q < 4; q++) acc[i][j][q] = 0.0f;

    // --- ldmatrix per-lane base addressing ---
    const int arow  = warp_m + (lane & 7) + ((lane >> 3) & 1) * 8;  // + mt*16
    const int akblk = (lane >> 4) & 1;
    const int ax    = arow & 3;
    const int brow  = warp_n + (lane & 7) + ((lane >> 4) & 1) * 8;  // + jj*16
    const int bkblk = (lane >> 3) & 1;
    const int bx    = brow & 3;

    #define AOFF(mt, kb) \
        (uint32_t)((arow + (mt) * 16) * 64 + (((((kb) >> 3) + akblk) ^ ax) & 3) * 16)
    #define BOFF(jj, kb) \
        (uint32_t)((brow + (jj) * 16) * 64 + (((((kb) >> 3) + bkblk) ^ bx) & 3) * 16)

    // --- cp.async stage load: 2 x 16B per array per thread (4 cp.async) ---
    const int c0row = tid >> 2,          c0ch = tid & 3;
    const int c1row = (tid + 256) >> 2;
    const uint32_t d0 = (uint32_t)(c0row * 64 + ((c0ch ^ (c0row & 3)) << 4));
    const uint32_t d1 = (uint32_t)(c1row * 64 + ((c0ch ^ (c1row & 3)) << 4));
    const size_t gA0 = (size_t)(m0 + c0row) * DD + c0ch * 8;
    const size_t gA1 = (size_t)(m0 + c1row) * DD + c0ch * 8;
    const size_t gB0 = (size_t)(n0 + c0row) * DD + c0ch * 8;
    const size_t gB1 = (size_t)(n0 + c1row) * DD + c0ch * 8;

    #define LOAD_STAGE(it, buf) do {                                     \
        const int _k0 = (it) * 32;                                       \
        const uint32_t _so = (uint32_t)(buf) * 8192u;                    \
        cp16(SA + _so + d0, A + gA0 + _k0);                              \
        cp16(SA + _so + d1, A + gA1 + _k0);                              \
        cp16(SB + _so + d0, B + gB0 + _k0);                              \
        cp16(SB + _so + d1, B + gB1 + _k0);                              \
        asm volatile("cp.async.commit_group;" ::: "memory");             \
    } while (0)

    LOAD_STAGE(0, 0);

    const int NK = DD / 32;   // 16
    for (int it = 0; it < NK; it++) {
        if (it + 1 < NK) {
            LOAD_STAGE(it + 1, (it + 1) & 1);
            asm volatile("cp.async.wait_group 1;" ::: "memory");
        } else {
            asm volatile("cp.async.wait_group 0;" ::: "memory");
        }
        __syncthreads();

        const uint32_t so = (uint32_t)(it & 1) * 8192u;
        #pragma unroll
        for (int ks = 0; ks < 2; ks++) {
            const int kb = ks * 16;
            uint32_t af[2][4];
            #pragma unroll
            for (int mt = 0; mt < 2; mt++)
                ldm_x4(af[mt], SA + so + AOFF(mt, kb));
            uint32_t bf[4][4];
            #pragma unroll
            for (int jj = 0; jj < 4; jj++)
                ldm_x4(bf[jj], SB + so + BOFF(jj, kb));
            #pragma unroll
            for (int j = 0; j < 8; j++) {
                const int jj = j >> 1, jh = (j & 1) * 2;
                const uint32_t b0 = bf[jj][jh], b1 = bf[jj][jh + 1];
                #pragma unroll
                for (int mt = 0; mt < 2; mt++)
                    mma_fp16(acc[mt][j], af[mt], b0, b1);
            }
        }
        __syncthreads();
    }
    #undef LOAD_STAGE
    #undef AOFF
    #undef BOFF

    // Epilogue: direct global float2 stores
    #pragma unroll
    for (int mt = 0; mt < 2; mt++) {
        const int row = m0 + warp_m + mt * 16 + (lane >> 2);
        #pragma unroll
        for (int j = 0; j < 8; j++) {
            const int col = n0 + warp_n + j * 8 + (lane & 3) * 2;
            float v0 = acc[mt][j][0], v1 = acc[mt][j][1];
            float v2 = acc[mt][j][2], v3 = acc[mt][j][3];
            if (TANH) { v0 = tanhf(v0); v1 = tanhf(v1); v2 = tanhf(v2); v3 = tanhf(v3); }
            *reinterpret_cast<float2*>(C + (size_t)row * OO + col)       = make_float2(v0, v1);
            *reinterpret_cast<float2*>(C + (size_t)(row + 8) * OO + col) = make_float2(v2, v3);
        }
    }
}

// ---------------------------------------------------------------------------
// Masked softmax over axis=1 (N=256), in-place on out[B, N, O].
// grid (BB, 4): each block handles 128 output channels with 128 threads.
// Online max/sum (2 passes over data instead of 3).
// ---------------------------------------------------------------------------
__global__ __launch_bounds__(128)
void softmax_kernel(float* __restrict__ out, const unsigned* __restrict__ mask) {
    const int b = blockIdx.x;
    const int o = blockIdx.y * 128 + threadIdx.x;

    __shared__ unsigned smask[NN];
    if (threadIdx.x < 128) {
        smask[threadIdx.x]       = mask[(size_t)b * NN + threadIdx.x];
        smask[threadIdx.x + 128] = mask[(size_t)b * NN + threadIdx.x + 128];
    }
    __syncthreads();

    int my = (smask[threadIdx.x] != 0u) | (smask[threadIdx.x + 128] != 0u);
    int any = __syncthreads_or(my);
    if (!any && threadIdx.x == 0) smask[0] = 1u;
    __syncthreads();

    float* base = out + (size_t)b * NN * OO + o;

    // Online max + sum in one pass
    float m = -INFINITY, s = 0.0f;
    for (int n = 0; n < NN; n++) {
        if (smask[n]) {
            float v = base[(size_t)n * OO];
            float nm = fmaxf(m, v);
            s = s * __expf(m - nm) + __expf(v - nm);
            m = nm;
        }
    }

    const float rs = 1.0f / s;
    for (int n = 0; n < NN; n++) {
        float v = smask[n] ? __expf(base[(size_t)n * OO] - m) * rs : 0.0f;
        base[(size_t)n * OO] = v;
    }
}

// ---------------------------------------------------------------------------
// Launch
// ---------------------------------------------------------------------------
extern "C" void kernel_launch(void* const* d_in, const int* in_sizes, int n_in,
                              void* d_out, int out_size) {
    const float*    Obs  = (const float*)d_in[0];
    const unsigned* mask = (const unsigned*)d_in[1];
    const float* g1 = (const float*)d_in[2];
    const float* b1 = (const float*)d_in[3];
    const float* W1 = (const float*)d_in[4];
    const float* g2 = (const float*)d_in[5];
    const float* b2 = (const float*)d_in[6];
    const float* W2 = (const float*)d_in[7];
    const float* g3 = (const float*)d_in[8];
    const float* b3 = (const float*)d_in[9];
    const float* W3 = (const float*)d_in[10];
    float* out = (float*)d_out;

    float *h1, *h2;
    __half *a, *w;
    cudaGetSymbolAddress((void**)&h1, g_h1);
    cudaGetSymbolAddress((void**)&h2, g_h2);
    cudaGetSymbolAddress((void**)&a, g_a);
    cudaGetSymbolAddress((void**)&w, g_w);

    static bool attr_done = false;
    const int DSMEM = 32768;   // 2 arrays x 2 stages x 8192
    if (!attr_done) {
        cudaFuncSetAttribute(gemm_hmma_kernel<true>,
                             cudaFuncAttributeMaxDynamicSharedMemorySize, DSMEM);
        cudaFuncSetAttribute(gemm_hmma_kernel<false>,
                             cudaFuncAttributeMaxDynamicSharedMemorySize, DSMEM);
        attr_done = true;
    }

    const dim3 gGemm(OO / 128, MROWS / 128);

    // Block 1
    ln_fp16_kernel<<<MROWS, 128>>>(Obs, nullptr, g1, b1, a);
    wconv_kernel<<<(DD * OO) / 256, 256>>>(W1, w);
    gemm_hmma_kernel<true><<<gGemm, 256, DSMEM>>>(a, w, h1);

    // Block 2
    ln_fp16_kernel<<<MROWS, 128>>>(h1, nullptr, g2, b2, a);
    wconv_kernel<<<(DD * OO) / 256, 256>>>(W2, w);
    gemm_hmma_kernel<true><<<gGemm, 256, DSMEM>>>(a, w, h2);

    // Block 3 (residual input h2 + h1, no activation)
    ln_fp16_kernel<<<MROWS, 128>>>(h2, h1, g3, b3, a);
    wconv_kernel<<<(DD * OO) / 256, 256>>>(W3, w);
    gemm_hmma_kernel<false><<<gGemm, 256, DSMEM>>>(a, w, out);

    // Masked softmax over axis=1, in place
    softmax_kernel<<<dim3(BB, 4), 128>>>(out, mask);
}

// round 7
// speedup vs baseline: 3.6959x; 1.0028x over previous
#include <cuda_runtime.h>
#include <cuda_fp16.h>
#include <math.h>
#include <stdint.h>

#define BB 128
#define NN 256
#define DD 512
#define OO 512
#define MROWS (BB * NN)   // 32768

// ---------------------------------------------------------------------------
// Scratch (no cudaMalloc allowed)
// ---------------------------------------------------------------------------
__device__ float g_h1[(size_t)MROWS * OO];
__device__ float g_h2[(size_t)MROWS * OO];
__device__ __half g_a[(size_t)MROWS * DD];
__device__ __half g_w[(size_t)DD * OO];   // W^T: [N][K] fp16

// ---------------------------------------------------------------------------
// Helpers (sm_80-era PTX only — must assemble under compute_103)
// ---------------------------------------------------------------------------
__device__ __forceinline__ uint32_t smem_to_u32(const void* p) {
    uint32_t a;
    asm("{ .reg .u64 t; cvta.to.shared.u64 t, %1; cvt.u32.u64 %0, t; }"
        : "=r"(a) : "l"(p));
    return a;
}
__device__ __forceinline__ void cp16(uint32_t dst, const void* src) {
    asm volatile("cp.async.cg.shared.global [%0], [%1], 16;"
                 :: "r"(dst), "l"(src) : "memory");
}
__device__ __forceinline__ void ldm_x4(uint32_t* r, uint32_t addr) {
    asm volatile("ldmatrix.sync.aligned.m8n8.x4.shared.b16 {%0,%1,%2,%3}, [%4];"
                 : "=r"(r[0]), "=r"(r[1]), "=r"(r[2]), "=r"(r[3]) : "r"(addr));
}
__device__ __forceinline__ void mma_fp16(float* c, const uint32_t* a,
                                         uint32_t b0, uint32_t b1) {
    asm volatile(
        "mma.sync.aligned.m16n8k16.row.col.f32.f16.f16.f32 "
        "{%0,%1,%2,%3}, {%4,%5,%6,%7}, {%8,%9}, {%0,%1,%2,%3};"
        : "+f"(c[0]), "+f"(c[1]), "+f"(c[2]), "+f"(c[3])
        : "r"(a[0]), "r"(a[1]), "r"(a[2]), "r"(a[3]), "r"(b0), "r"(b1));
}

// ---------------------------------------------------------------------------
// LayerNorm -> fp16. Optional residual x2.
// ---------------------------------------------------------------------------
__global__ void ln_fp16_kernel(const float* __restrict__ x,
                               const float* __restrict__ x2,
                               const float* __restrict__ g,
                               const float* __restrict__ b,
                               __half* __restrict__ y) {
    const int row = blockIdx.x;
    const int tid = threadIdx.x;

    float4 v = reinterpret_cast<const float4*>(x + (size_t)row * DD)[tid];
    if (x2 != nullptr) {
        float4 v2 = reinterpret_cast<const float4*>(x2 + (size_t)row * DD)[tid];
        v.x += v2.x; v.y += v2.y; v.z += v2.z; v.w += v2.w;
    }

    float s  = v.x + v.y + v.z + v.w;
    float ss = v.x * v.x + v.y * v.y + v.z * v.z + v.w * v.w;
    #pragma unroll
    for (int o = 16; o > 0; o >>= 1) {
        s  += __shfl_xor_sync(0xFFFFFFFFu, s,  o);
        ss += __shfl_xor_sync(0xFFFFFFFFu, ss, o);
    }
    __shared__ float sh_s[4], sh_ss[4];
    const int w = tid >> 5;
    if ((tid & 31) == 0) { sh_s[w] = s; sh_ss[w] = ss; }
    __syncthreads();
    s  = sh_s[0] + sh_s[1] + sh_s[2] + sh_s[3];
    ss = sh_ss[0] + sh_ss[1] + sh_ss[2] + sh_ss[3];

    const float mean = s * (1.0f / DD);
    const float var  = ss * (1.0f / DD) - mean * mean;
    const float r    = rsqrtf(var + 1e-5f);

    const float4 gv = reinterpret_cast<const float4*>(g)[tid];
    const float4 bv = reinterpret_cast<const float4*>(b)[tid];
    float o0 = (v.x - mean) * r * gv.x + bv.x;
    float o1 = (v.y - mean) * r * gv.y + bv.y;
    float o2 = (v.z - mean) * r * gv.z + bv.z;
    float o3 = (v.w - mean) * r * gv.w + bv.w;

    __half2* ph = reinterpret_cast<__half2*>(y + (size_t)row * DD);
    ph[tid * 2]     = __halves2half2(__float2half_rn(o0), __float2half_rn(o1));
    ph[tid * 2 + 1] = __halves2half2(__float2half_rn(o2), __float2half_rn(o3));
}

// ---------------------------------------------------------------------------
// Weight convert+transpose: W[K,N] f32 -> Wt [N,K] fp16
// ---------------------------------------------------------------------------
__global__ void wconv_kernel(const float* __restrict__ W,
                             __half* __restrict__ o) {
    int idx = blockIdx.x * 256 + threadIdx.x;
    int k = idx >> 9, n = idx & 511;
    o[(size_t)n * DD + k] = __float2half_rn(W[idx]);
}

// ---------------------------------------------------------------------------
// fp16 HMMA GEMM: C[M,N] = A[M,K] @ B^T, B in [N,K] fp16.
// CTA 128x128, BK=32, 3-stage cp.async pipeline (one barrier per iteration),
// 8 warps (32x64 each).
// SMEM per stage (16KB): A tile at +0 (8KB), B tile at +8192.
// Tile layout: 128 rows x 64B, 16B chunks XOR-swizzled:
//   byte(row, k) = row*64 + (((k>>3) ^ (row&3)) & 3)*16 + (k&7)*2
// ---------------------------------------------------------------------------
template <bool TANH>
__global__ __launch_bounds__(256, 2)
void gemm_hmma_kernel(const __half* __restrict__ A,
                      const __half* __restrict__ B,
                      float* __restrict__ C) {
    extern __shared__ char smem[];
    const uint32_t sb = smem_to_u32(smem);

    const int tid  = threadIdx.x;
    const int lane = tid & 31;
    const int wid  = tid >> 5;
    const int m0 = blockIdx.y * 128;
    const int n0 = blockIdx.x * 128;
    const int warp_m = (wid >> 1) * 32;   // 0,32,64,96
    const int warp_n = (wid & 1) * 64;    // 0,64

    float acc[2][8][4];
    #pragma unroll
    for (int i = 0; i < 2; i++)
        #pragma unroll
        for (int j = 0; j < 8; j++)
            #pragma unroll
            for (int q = 0; q < 4; q++) acc[i][j][q] = 0.0f;

    // --- ldmatrix per-lane base addressing ---
    const int arow  = warp_m + (lane & 7) + ((lane >> 3) & 1) * 8;  // + mt*16
    const int akblk = (lane >> 4) & 1;
    const int ax    = arow & 3;
    const int brow  = warp_n + (lane & 7) + ((lane >> 4) & 1) * 8;  // + jj*16
    const int bkblk = (lane >> 3) & 1;
    const int bx    = brow & 3;

    #define AOFF(mt, kb) \
        (uint32_t)((arow + (mt) * 16) * 64 + (((((kb) >> 3) + akblk) ^ ax) & 3) * 16)
    #define BOFF(jj, kb) \
        (uint32_t)((brow + (jj) * 16) * 64 + (((((kb) >> 3) + bkblk) ^ bx) & 3) * 16)

    // --- cp.async stage load: 2 x 16B per array per thread (4 cp.async) ---
    const int c0row = tid >> 2,          c0ch = tid & 3;
    const int c1row = (tid + 256) >> 2;
    const uint32_t d0 = (uint32_t)(c0row * 64 + ((c0ch ^ (c0row & 3)) << 4));
    const uint32_t d1 = (uint32_t)(c1row * 64 + ((c0ch ^ (c1row & 3)) << 4));
    const size_t gA0 = (size_t)(m0 + c0row) * DD + c0ch * 8;
    const size_t gA1 = (size_t)(m0 + c1row) * DD + c0ch * 8;
    const size_t gB0 = (size_t)(n0 + c0row) * DD + c0ch * 8;
    const size_t gB1 = (size_t)(n0 + c1row) * DD + c0ch * 8;

    // stage s base: sb + s*16384; A at +0, B at +8192
    #define LOAD_STAGE(it, st) do {                                      \
        const int _k0 = (it) * 32;                                       \
        const uint32_t _sa = sb + (uint32_t)(st) * 16384u;               \
        const uint32_t _sbb = _sa + 8192u;                               \
        cp16(_sa + d0, A + gA0 + _k0);                                   \
        cp16(_sa + d1, A + gA1 + _k0);                                   \
        cp16(_sbb + d0, B + gB0 + _k0);                                  \
        cp16(_sbb + d1, B + gB1 + _k0);                                  \
        asm volatile("cp.async.commit_group;" ::: "memory");             \
    } while (0)

    LOAD_STAGE(0, 0);
    LOAD_STAGE(1, 1);

    const int NK = DD / 32;   // 16
    int st = 0;               // stage of iteration it
    for (int it = 0; it < NK; it++) {
        if (it + 1 < NK) {
            asm volatile("cp.async.wait_group 1;" ::: "memory");
        } else {
            asm volatile("cp.async.wait_group 0;" ::: "memory");
        }
        __syncthreads();

        // Prefetch 2 ahead into the stage freed last iteration.
        if (it + 2 < NK) {
            int st2 = st + 2; if (st2 >= 3) st2 -= 3;
            LOAD_STAGE(it + 2, st2);
        }

        const uint32_t sa = sb + (uint32_t)st * 16384u;
        const uint32_t sbB = sa + 8192u;
        #pragma unroll
        for (int ks = 0; ks < 2; ks++) {
            const int kb = ks * 16;
            uint32_t af[2][4];
            #pragma unroll
            for (int mt = 0; mt < 2; mt++)
                ldm_x4(af[mt], sa + AOFF(mt, kb));
            uint32_t bf[4][4];
            #pragma unroll
            for (int jj = 0; jj < 4; jj++)
                ldm_x4(bf[jj], sbB + BOFF(jj, kb));
            #pragma unroll
            for (int j = 0; j < 8; j++) {
                const int jj = j >> 1, jh = (j & 1) * 2;
                const uint32_t b0 = bf[jj][jh], b1 = bf[jj][jh + 1];
                #pragma unroll
                for (int mt = 0; mt < 2; mt++)
                    mma_fp16(acc[mt][j], af[mt], b0, b1);
            }
        }
        if (++st >= 3) st = 0;
    }
    #undef LOAD_STAGE
    #undef AOFF
    #undef BOFF

    // Epilogue: direct global float2 stores
    #pragma unroll
    for (int mt = 0; mt < 2; mt++) {
        const int row = m0 + warp_m + mt * 16 + (lane >> 2);
        #pragma unroll
        for (int j = 0; j < 8; j++) {
            const int col = n0 + warp_n + j * 8 + (lane & 3) * 2;
            float v0 = acc[mt][j][0], v1 = acc[mt][j][1];
            float v2 = acc[mt][j][2], v3 = acc[mt][j][3];
            if (TANH) { v0 = tanhf(v0); v1 = tanhf(v1); v2 = tanhf(v2); v3 = tanhf(v3); }
            *reinterpret_cast<float2*>(C + (size_t)row * OO + col)       = make_float2(v0, v1);
            *reinterpret_cast<float2*>(C + (size_t)(row + 8) * OO + col) = make_float2(v2, v3);
        }
    }
}

// ---------------------------------------------------------------------------
// Masked softmax over axis=1 (N=256), in-place on out[B, N, O].
// grid (BB, 4): each block handles 128 output channels with 128 threads.
// Online max/sum (2 passes over data instead of 3).
// ---------------------------------------------------------------------------
__global__ __launch_bounds__(128)
void softmax_kernel(float* __restrict__ out, const unsigned* __restrict__ mask) {
    const int b = blockIdx.x;
    const int o = blockIdx.y * 128 + threadIdx.x;

    __shared__ unsigned smask[NN];
    if (threadIdx.x < 128) {
        smask[threadIdx.x]       = mask[(size_t)b * NN + threadIdx.x];
        smask[threadIdx.x + 128] = mask[(size_t)b * NN + threadIdx.x + 128];
    }
    __syncthreads();

    int my = (smask[threadIdx.x] != 0u) | (smask[threadIdx.x + 128] != 0u);
    int any = __syncthreads_or(my);
    if (!any && threadIdx.x == 0) smask[0] = 1u;
    __syncthreads();

    float* base = out + (size_t)b * NN * OO + o;

    // Online max + sum in one pass
    float m = -INFINITY, s = 0.0f;
    for (int n = 0; n < NN; n++) {
        if (smask[n]) {
            float v = base[(size_t)n * OO];
            float nm = fmaxf(m, v);
            s = s * __expf(m - nm) + __expf(v - nm);
            m = nm;
        }
    }

    const float rs = 1.0f / s;
    for (int n = 0; n < NN; n++) {
        float v = smask[n] ? __expf(base[(size_t)n * OO] - m) * rs : 0.0f;
        base[(size_t)n * OO] = v;
    }
}

// ---------------------------------------------------------------------------
// Launch
// ---------------------------------------------------------------------------
extern "C" void kernel_launch(void* const* d_in, const int* in_sizes, int n_in,
                              void* d_out, int out_size) {
    const float*    Obs  = (const float*)d_in[0];
    const unsigned* mask = (const unsigned*)d_in[1];
    const float* g1 = (const float*)d_in[2];
    const float* b1 = (const float*)d_in[3];
    const float* W1 = (const float*)d_in[4];
    const float* g2 = (const float*)d_in[5];
    const float* b2 = (const float*)d_in[6];
    const float* W2 = (const float*)d_in[7];
    const float* g3 = (const float*)d_in[8];
    const float* b3 = (const float*)d_in[9];
    const float* W3 = (const float*)d_in[10];
    float* out = (float*)d_out;

    float *h1, *h2;
    __half *a, *w;
    cudaGetSymbolAddress((void**)&h1, g_h1);
    cudaGetSymbolAddress((void**)&h2, g_h2);
    cudaGetSymbolAddress((void**)&a, g_a);
    cudaGetSymbolAddress((void**)&w, g_w);

    static bool attr_done = false;
    const int DSMEM = 49152;   // 3 stages x 16KB
    if (!attr_done) {
        cudaFuncSetAttribute(gemm_hmma_kernel<true>,
                             cudaFuncAttributeMaxDynamicSharedMemorySize, DSMEM);
        cudaFuncSetAttribute(gemm_hmma_kernel<false>,
                             cudaFuncAttributeMaxDynamicSharedMemorySize, DSMEM);
        attr_done = true;
    }

    const dim3 gGemm(OO / 128, MROWS / 128);

    // Block 1
    ln_fp16_kernel<<<MROWS, 128>>>(Obs, nullptr, g1, b1, a);
    wconv_kernel<<<(DD * OO) / 256, 256>>>(W1, w);
    gemm_hmma_kernel<true><<<gGemm, 256, DSMEM>>>(a, w, h1);

    // Block 2
    ln_fp16_kernel<<<MROWS, 128>>>(h1, nullptr, g2, b2, a);
    wconv_kernel<<<(DD * OO) / 256, 256>>>(W2, w);
    gemm_hmma_kernel<true><<<gGemm, 256, DSMEM>>>(a, w, h2);

    // Block 3 (residual input h2 + h1, no activation)
    ln_fp16_kernel<<<MROWS, 128>>>(h2, h1, g3, b3, a);
    wconv_kernel<<<(DD * OO) / 256, 256>>>(W3, w);
    gemm_hmma_kernel<false><<<gGemm, 256, DSMEM>>>(a, w, out);

    // Masked softmax over axis=1, in place
    softmax_kernel<<<dim3(BB, 4), 128>>>(out, mask);
}